// round 13
// baseline (speedup 1.0000x reference)
#include <cuda_runtime.h>
#include <cuda_bf16.h>
#include <mma.h>
#include <math.h>
#include <cstdint>

using namespace nvcuda;

// Problem constants
#define BB 4
#define LL 4092
#define HH 8
#define DH 64
#define DM 512
#define WS 12
#define STEP 6
#define NW 681
#define LNEPS 1e-5f
#define TPB_TOK 42
#define NG 98              // ceil(4092/42)

// ---------------- scratch -----------------
__device__ float g_att[BB*LL*DM];         // averaged attn out [B,L,H*64]
__device__ __nv_bfloat16 g_Wh[3*64*64];   // transposed [m][d][e] bf16 hi
__device__ __nv_bfloat16 g_Wl[3*64*64];   // transposed [m][d][e] bf16 lo

// ---------------- packed f32x2 helpers ----------------
__device__ __forceinline__ unsigned long long ffma2(
    unsigned long long a, unsigned long long b, unsigned long long c) {
    unsigned long long d;
    asm("fma.rn.f32x2 %0, %1, %2, %3;" : "=l"(d) : "l"(a), "l"(b), "l"(c));
    return d;
}
__device__ __forceinline__ unsigned long long pack2(float x, float y) {
    unsigned long long d;
    asm("mov.b64 %0, {%1, %2};" : "=l"(d)
        : "r"(__float_as_uint(x)), "r"(__float_as_uint(y)));
    return d;
}
__device__ __forceinline__ void unpack2(unsigned long long p, float& x, float& y) {
    unsigned int lo, hi;
    asm("mov.b64 {%0, %1}, %2;" : "=r"(lo), "=r"(hi) : "l"(p));
    x = __uint_as_float(lo); y = __uint_as_float(hi);
}

// =============================================================================
// Kernel 0: W -> transposed bf16 hi/lo.
// =============================================================================
__global__ __launch_bounds__(256) void prep_kernel(
    const float* __restrict__ Wq, const float* __restrict__ Wk, const float* __restrict__ Wv)
{
    const int m = blockIdx.x;
    const float* W = (m == 0) ? Wq : (m == 1) ? Wk : Wv;
    for (int idx = threadIdx.x; idx < 4096; idx += 256) {
        int e = idx >> 6, d = idx & 63;
        float w = W[idx];
        __nv_bfloat16 hi = __float2bfloat16(w);
        __nv_bfloat16 lo = __float2bfloat16(w - __bfloat162float(hi));
        g_Wh[m*4096 + d*64 + e] = hi;
        g_Wl[m*4096 + d*64 + e] = lo;
    }
}

// =============================================================================
// Fused kernel: per-block wmma projection of a 64-row span (3 matrices) into
// smem, then windowed attention + overlap-add finalization (R8 logic).
// 256 threads = 8 warps. Warp w: row strip (w>>1)*16, n-half (w&1)*2.
// smem (floats): Qs/Ks/Vs [64][68] fp32 (13056) + staging sXh/sXl bf16 [64][72]
// (4608 f; P overlays) + sWh/sWl bf16 [64][72] (4608 f)  = 22272 f = 89088 B.
// =============================================================================
#define ATT_SMEM_FLOATS (3*64*68 + 4608 + 4608)   // 22272 -> 89088 B

__global__ __launch_bounds__(256) void fused_attn_kernel(
    const float* __restrict__ q, const float* __restrict__ k, const float* __restrict__ v,
    float* __restrict__ attn_out)
{
    extern __shared__ float smf[];
    float* Qs = smf;                       // 64*68
    float* Ks = Qs + 64*68;
    float* Vs = Ks + 64*68;
    float* stage_f = smf + 3*64*68;
    __nv_bfloat16* sXh = reinterpret_cast<__nv_bfloat16*>(stage_f);       // 64*72
    __nv_bfloat16* sXl = sXh + 64*72;
    float* P = stage_f;                    // overlay (1152 <= 4608 floats)
    __nv_bfloat16* sWh = reinterpret_cast<__nv_bfloat16*>(stage_f + 4608); // 64*72
    __nv_bfloat16* sWl = sWh + 64*72;

    const int tid = threadIdx.x;
    const int warp = tid >> 5;
    const int rs = (warp >> 1) * 16;       // row strip
    const int nt0 = (warp & 1) * 2;        // first n-tile
    const int blk = blockIdx.x;
    const int bh = blk / NG;
    const int g  = blk - bh * NG;
    const int b  = bh >> 3;
    const int h  = bh & 7;

    const int t_start = g * TPB_TOK;
    const int ntok = (LL - t_start < TPB_TOK) ? (LL - t_start) : TPB_TOK;
    const int n_lo = (7*g - 1 < 0) ? 0 : 7*g - 1;
    const int n_hi = (7*g + 6 > NW-1) ? NW-1 : 7*g + 6;
    const int nwin = n_hi - n_lo + 1;
    const int row0 = n_lo * 6;

    // ======== fused projection: for each of Q/K/V ========
    const float* Xsrc[3] = {q, k, v};
    float* Dst[3] = {Qs, Ks, Vs};

    #pragma unroll
    for (int m = 0; m < 3; m++) {
        // ---- copy W_m (transposed bf16 hi/lo) into smem
        {
            const uint2* srcH = reinterpret_cast<const uint2*>(g_Wh + m*4096);
            const uint2* srcL = reinterpret_cast<const uint2*>(g_Wl + m*4096);
            for (int idx = tid; idx < 1024; idx += 256) {
                int d = idx >> 4, c4 = idx & 15;
                *reinterpret_cast<uint2*>(&sWh[d*72 + c4*4]) = srcH[idx];
                *reinterpret_cast<uint2*>(&sWl[d*72 + c4*4]) = srcL[idx];
            }
        }
        // ---- stage raw X rows (64, clamped) as bf16 hi/lo
        {
            const float* X = Xsrc[m];
            for (int idx = tid; idx < 1024; idx += 256) {
                int row = idx >> 4, c4 = idx & 15;
                int gr = row0 + row; if (gr > LL-1) gr = LL-1;
                float4 xv = reinterpret_cast<const float4*>(
                    X + ((size_t)(b*LL + gr)*HH + h)*64)[c4];
                float2 p0 = make_float2(xv.x, xv.y);
                float2 p1 = make_float2(xv.z, xv.w);
                __nv_bfloat162 h0 = __float22bfloat162_rn(p0);
                __nv_bfloat162 h1 = __float22bfloat162_rn(p1);
                float2 hf0 = __bfloat1622float2(h0);
                float2 hf1 = __bfloat1622float2(h1);
                __nv_bfloat162 l0 = __float22bfloat162_rn(make_float2(p0.x - hf0.x, p0.y - hf0.y));
                __nv_bfloat162 l1 = __float22bfloat162_rn(make_float2(p1.x - hf1.x, p1.y - hf1.y));
                uint32_t* dh = reinterpret_cast<uint32_t*>(&sXh[row*72 + c4*4]);
                uint32_t* dl = reinterpret_cast<uint32_t*>(&sXl[row*72 + c4*4]);
                dh[0] = *reinterpret_cast<uint32_t*>(&h0);
                dh[1] = *reinterpret_cast<uint32_t*>(&h1);
                dl[0] = *reinterpret_cast<uint32_t*>(&l0);
                dl[1] = *reinterpret_cast<uint32_t*>(&l1);
            }
        }
        __syncthreads();

        // ---- wmma: this warp's 16-row strip x 2 n-tiles
        {
            wmma::fragment<wmma::matrix_a, 16, 16, 16, __nv_bfloat16, wmma::row_major> a_hi[4], a_lo[4];
            #pragma unroll
            for (int kk = 0; kk < 4; kk++) {
                wmma::load_matrix_sync(a_hi[kk], &sXh[rs*72 + kk*16], 72);
                wmma::load_matrix_sync(a_lo[kk], &sXl[rs*72 + kk*16], 72);
            }
            float* D = Dst[m];
            #pragma unroll
            for (int ni = 0; ni < 2; ni++) {
                int n = nt0 + ni;
                wmma::fragment<wmma::accumulator, 16, 16, 16, float> acc;
                wmma::fill_fragment(acc, 0.0f);
                #pragma unroll
                for (int kk = 0; kk < 4; kk++) {
                    wmma::fragment<wmma::matrix_b, 16, 16, 16, __nv_bfloat16, wmma::row_major> b_hi, b_lo;
                    wmma::load_matrix_sync(b_hi, &sWh[(kk*16)*72 + n*16], 72);
                    wmma::load_matrix_sync(b_lo, &sWl[(kk*16)*72 + n*16], 72);
                    wmma::mma_sync(acc, a_hi[kk], b_hi, acc);
                    wmma::mma_sync(acc, a_hi[kk], b_lo, acc);
                    wmma::mma_sync(acc, a_lo[kk], b_hi, acc);
                }
                wmma::store_matrix_sync(&D[rs*68 + n*16], acc, 68, wmma::mem_row_major);
            }
        }
        __syncthreads();   // staging reused next m; Dst visible afterwards
    }

    // ======== attention (R8 logic; Qs/Ks/Vs stride 68) ========
    for (int o = tid; o < nwin*144; o += 256) {
        int w = o / 144;
        int r = o - w*144;
        int qi = r / 12, ki = r - qi*12;
        const float* qr = &Qs[(w*6 + qi)*68];
        const float* kr = &Ks[(w*6 + ki)*68];
        unsigned long long s01 = 0ULL, s23 = 0ULL;
        #pragma unroll
        for (int d = 0; d < 64; d += 4) {
            float4 a = *reinterpret_cast<const float4*>(&qr[d]);
            float4 bb = *reinterpret_cast<const float4*>(&kr[d]);
            s01 = ffma2(pack2(a.x, a.y), pack2(bb.x, bb.y), s01);
            s23 = ffma2(pack2(a.z, a.w), pack2(bb.z, bb.w), s23);
        }
        float x0, x1, x2, x3;
        unpack2(s01, x0, x1); unpack2(s23, x2, x3);
        P[o] = (x0 + x1 + x2 + x3) * 0.125f;   // NOTE: P overlays staging — after sync
    }
    __syncthreads();

    for (int t = tid; t < nwin*12; t += 256) {
        int w = t / 12, qi = t - w*12;
        float* row = &P[w*144 + qi*12];
        float mx = row[0];
        #pragma unroll
        for (int k2 = 1; k2 < 12; k2++) mx = fmaxf(mx, row[k2]);
        float sum = 0.f;
        float e[12];
        #pragma unroll
        for (int k2 = 0; k2 < 12; k2++) { e[k2] = __expf(row[k2] - mx); sum += e[k2]; }
        float inv = 1.f / sum;
        #pragma unroll
        for (int k2 = 0; k2 < 12; k2++) row[k2] = e[k2] * inv;
    }
    __syncthreads();

    if (attn_out) {
        int wn0 = 7*g;
        int wn1 = (7*g + 7 < NW) ? 7*g + 7 : NW;
        int nw_out = wn1 - wn0;
        float* dst = attn_out + ((size_t)bh*NW + wn0)*144;
        const float* src = P + (wn0 - n_lo)*144;
        for (int o = tid; o < nw_out*144; o += 256) dst[o] = src[o];
    }

    for (int item = tid; item < ntok*16; item += 256) {
        int t  = t_start + (item >> 4);
        int e4 = (item & 15) * 4;
        int n1 = t / 6;

        unsigned long long a01 = 0ULL, a23 = 0ULL;
        float cnt = 0.f;
        if (n1 <= n_hi) {
            int wi = n1 - n_lo;
            int qq = t - n1*6;
            const float* prow = &P[wi*144 + qq*12];
            const float* vb = &Vs[(wi*6)*68 + e4];
            #pragma unroll
            for (int k2 = 0; k2 < 12; k2++) {
                float4 vv = *reinterpret_cast<const float4*>(&vb[k2*68]);
                unsigned long long pk = pack2(prow[k2], prow[k2]);
                a01 = ffma2(pk, pack2(vv.x, vv.y), a01);
                a23 = ffma2(pk, pack2(vv.z, vv.w), a23);
            }
            cnt += 1.f;
        }
        if (n1 >= 1 && n1 - 1 >= n_lo) {
            int wi = n1 - 1 - n_lo;
            int qq = t - (n1-1)*6;
            const float* prow = &P[wi*144 + qq*12];
            const float* vb = &Vs[(wi*6)*68 + e4];
            #pragma unroll
            for (int k2 = 0; k2 < 12; k2++) {
                float4 vv = *reinterpret_cast<const float4*>(&vb[k2*68]);
                unsigned long long pk = pack2(prow[k2], prow[k2]);
                a01 = ffma2(pk, pack2(vv.x, vv.y), a01);
                a23 = ffma2(pk, pack2(vv.z, vv.w), a23);
            }
            cnt += 1.f;
        }
        float inv = 1.f / cnt;
        float o0, o1, o2, o3;
        unpack2(a01, o0, o1); unpack2(a23, o2, o3);
        *reinterpret_cast<float4*>(
            &g_att[((size_t)(b*LL + t)*HH + h)*64 + e4]) =
            make_float4(o0*inv, o1*inv, o2*inv, o3*inv);
    }
}

// =============================================================================
// Kernel 3: residual + LayerNorm over dense g_att [B,L,512]
// =============================================================================
__global__ __launch_bounds__(128) void combine_kernel(
    const float* __restrict__ queries, const float* __restrict__ gamma,
    const float* __restrict__ beta, float* __restrict__ z)
{
    __shared__ float red[8];

    const int tid = threadIdx.x;
    const int tok = blockIdx.x;
    const int c0 = tid * 4;

    float4 a = *reinterpret_cast<const float4*>(&g_att[(size_t)tok*DM + c0]);
    float4 resid = *reinterpret_cast<const float4*>(&queries[(size_t)tok*DM + c0]);
    float4 x;
    x.x = a.x + resid.x; x.y = a.y + resid.y;
    x.z = a.z + resid.z; x.w = a.w + resid.w;

    float s  = x.x + x.y + x.z + x.w;
    float ss = x.x*x.x + x.y*x.y + x.z*x.z + x.w*x.w;
    #pragma unroll
    for (int off = 16; off > 0; off >>= 1) {
        s  += __shfl_down_sync(0xFFFFFFFFu, s, off);
        ss += __shfl_down_sync(0xFFFFFFFFu, ss, off);
    }
    int wid = tid >> 5, lane = tid & 31;
    if (lane == 0) { red[wid] = s; red[4 + wid] = ss; }
    __syncthreads();
    float ts  = red[0] + red[1] + red[2] + red[3];
    float tss = red[4] + red[5] + red[6] + red[7];
    float mean = ts * (1.f / DM);
    float var  = tss * (1.f / DM) - mean*mean;
    float rstd = rsqrtf(var + LNEPS);

    float4 gg = *reinterpret_cast<const float4*>(&gamma[c0]);
    float4 bta = *reinterpret_cast<const float4*>(&beta[c0]);
    float4 o;
    o.x = (x.x - mean)*rstd*gg.x + bta.x;
    o.y = (x.y - mean)*rstd*gg.y + bta.y;
    o.z = (x.z - mean)*rstd*gg.z + bta.z;
    o.w = (x.w - mean)*rstd*gg.w + bta.w;
    *reinterpret_cast<float4*>(&z[(size_t)tok*DM + c0]) = o;
}

// =============================================================================
extern "C" void kernel_launch(void* const* d_in, const int* in_sizes, int n_in,
                              void* d_out, int out_size) {
    const float* queries = (const float*)d_in[0];
    const float* keys    = (const float*)d_in[1];
    const float* values  = (const float*)d_in[2];
    const float* Wq      = (const float*)d_in[3];
    const float* Wk      = (const float*)d_in[4];
    const float* Wv      = (const float*)d_in[5];
    const float* gamma   = (const float*)d_in[6];
    const float* beta    = (const float*)d_in[7];

    float* z = (float*)d_out;
    const long Z = (long)BB * LL * DM;
    const long A = (long)BB * HH * NW * WS * WS;
    float* attn_out = nullptr;
    if ((long)out_size >= Z + A) attn_out = z + Z;

    const int attn_smem = ATT_SMEM_FLOATS * 4;   // 89088 B
    static bool attr_set = false;
    if (!attr_set) {
        cudaFuncSetAttribute(fused_attn_kernel,
                             cudaFuncAttributeMaxDynamicSharedMemorySize, attn_smem);
        attr_set = true;
    }

    prep_kernel<<<3, 256>>>(Wq, Wk, Wv);
    fused_attn_kernel<<<BB*HH*NG, 256, attn_smem>>>(queries, keys, values, attn_out);
    combine_kernel<<<BB*LL, 128>>>(queries, gamma, beta, z);
}

// round 15
// speedup vs baseline: 1.2975x; 1.2975x over previous
#include <cuda_runtime.h>
#include <cuda_bf16.h>
#include <mma.h>
#include <math.h>
#include <cstdint>

using namespace nvcuda;

// Problem constants
#define BB 4
#define LL 4092
#define HH 8
#define DH 64
#define DM 512
#define WS 12
#define STEP 6
#define NW 681
#define MROWS (BB*LL*HH)   // 130944
#define LNEPS 1e-5f
#define TPB_TOK 42
#define NG 98              // ceil(4092/42)

// ---------------- scratch -----------------
__device__ float g_Qp[MROWS*DH];          // [B,L,H,64]
__device__ float g_Kp[MROWS*DH];
__device__ float g_Vp[MROWS*DH];
__device__ float g_att[BB*LL*DM];         // averaged attn out [B,L,H*64]

// ---------------- packed f32x2 helpers ----------------
__device__ __forceinline__ unsigned long long ffma2(
    unsigned long long a, unsigned long long b, unsigned long long c) {
    unsigned long long d;
    asm("fma.rn.f32x2 %0, %1, %2, %3;" : "=l"(d) : "l"(a), "l"(b), "l"(c));
    return d;
}
__device__ __forceinline__ unsigned long long pack2(float x, float y) {
    unsigned long long d;
    asm("mov.b64 %0, {%1, %2};" : "=l"(d)
        : "r"(__float_as_uint(x)), "r"(__float_as_uint(y)));
    return d;
}
__device__ __forceinline__ void unpack2(unsigned long long p, float& x, float& y) {
    unsigned int lo, hi;
    asm("mov.b64 {%0, %1}, %2;" : "=r"(lo), "=r"(hi) : "l"(p));
    x = __uint_as_float(lo); y = __uint_as_float(hi);
}

// =============================================================================
// Kernel 1: projections via wmma bf16 split (Ah*Bh + Ah*Bl + Al*Bh).
// grid = (1023, 3). 256 threads = 8 warps; warp w -> rows [w*16, w*16+16).
// W converted to bf16 hi/lo in-block (overlaps X-load latency).
// Output written directly to global [M][64] from accumulator fragments.
// =============================================================================
#define A_STRIDE 72
#define B_STRIDE 72
#define SM_AH 0
#define SM_AL (128*A_STRIDE)
#define SM_BH (2*128*A_STRIDE)
#define SM_BL (2*128*A_STRIDE + 64*B_STRIDE)
#define PROJ_SMEM_BF16 (2*128*A_STRIDE + 2*64*B_STRIDE)   // 55296 B

__global__ __launch_bounds__(256) void proj_kernel(
    const float* __restrict__ q, const float* __restrict__ k, const float* __restrict__ v,
    const float* __restrict__ Wq, const float* __restrict__ Wk, const float* __restrict__ Wv)
{
    extern __shared__ __nv_bfloat16 smbf[];
    __nv_bfloat16* sAh = smbf + SM_AH;
    __nv_bfloat16* sAl = smbf + SM_AL;
    __nv_bfloat16* sBh = smbf + SM_BH;
    __nv_bfloat16* sBl = smbf + SM_BL;

    const int tid = threadIdx.x;
    const int warp = tid >> 5;
    const int r0 = blockIdx.x * 128;
    const int m  = blockIdx.y;

    const float* X = (m == 0) ? q : (m == 1) ? k : v;
    const float* W = (m == 0) ? Wq : (m == 1) ? Wk : Wv;
    float* Out = (m == 0) ? g_Qp : (m == 1) ? g_Kp : g_Vp;

    // ---- W -> bf16 hi/lo, transposed: sB*[d][e] = W[e][d]
    for (int idx = tid; idx < 4096; idx += 256) {
        int e = idx >> 6, d = idx & 63;
        float w = W[idx];
        __nv_bfloat16 hi = __float2bfloat16(w);
        __nv_bfloat16 lo = __float2bfloat16(w - __bfloat162float(hi));
        sBh[d*B_STRIDE + e] = hi;
        sBl[d*B_STRIDE + e] = lo;
    }
    // ---- X -> bf16 hi/lo (packed converts), row-major [128][72]
    for (int idx = tid; idx < 2048; idx += 256) {      // 2048 float4
        int row = idx >> 4, c4 = idx & 15;
        float4 xv = reinterpret_cast<const float4*>(X + (size_t)(r0 + row)*64)[c4];
        float2 p0 = make_float2(xv.x, xv.y);
        float2 p1 = make_float2(xv.z, xv.w);
        __nv_bfloat162 h0 = __float22bfloat162_rn(p0);
        __nv_bfloat162 h1 = __float22bfloat162_rn(p1);
        float2 hf0 = __bfloat1622float2(h0);
        float2 hf1 = __bfloat1622float2(h1);
        __nv_bfloat162 l0 = __float22bfloat162_rn(make_float2(p0.x - hf0.x, p0.y - hf0.y));
        __nv_bfloat162 l1 = __float22bfloat162_rn(make_float2(p1.x - hf1.x, p1.y - hf1.y));
        uint32_t* dh = reinterpret_cast<uint32_t*>(&sAh[row*A_STRIDE + c4*4]);
        uint32_t* dl = reinterpret_cast<uint32_t*>(&sAl[row*A_STRIDE + c4*4]);
        dh[0] = *reinterpret_cast<uint32_t*>(&h0);
        dh[1] = *reinterpret_cast<uint32_t*>(&h1);
        dl[0] = *reinterpret_cast<uint32_t*>(&l0);
        dl[1] = *reinterpret_cast<uint32_t*>(&l1);
    }
    __syncthreads();

    // ---- A fragments (4 k-tiles, hi+lo)
    wmma::fragment<wmma::matrix_a, 16, 16, 16, __nv_bfloat16, wmma::row_major> a_hi[4], a_lo[4];
    #pragma unroll
    for (int kk = 0; kk < 4; kk++) {
        wmma::load_matrix_sync(a_hi[kk], &sAh[(warp*16)*A_STRIDE + kk*16], A_STRIDE);
        wmma::load_matrix_sync(a_lo[kk], &sAl[(warp*16)*A_STRIDE + kk*16], A_STRIDE);
    }

    // ---- MMA: 4 n-tiles; store straight to global [M][64]
    float* wOut = Out + (size_t)(r0 + warp*16) * 64;
    #pragma unroll
    for (int n = 0; n < 4; n++) {
        wmma::fragment<wmma::accumulator, 16, 16, 16, float> acc;
        wmma::fill_fragment(acc, 0.0f);
        #pragma unroll
        for (int kk = 0; kk < 4; kk++) {
            wmma::fragment<wmma::matrix_b, 16, 16, 16, __nv_bfloat16, wmma::row_major> b_hi, b_lo;
            wmma::load_matrix_sync(b_hi, &sBh[(kk*16)*B_STRIDE + n*16], B_STRIDE);
            wmma::load_matrix_sync(b_lo, &sBl[(kk*16)*B_STRIDE + n*16], B_STRIDE);
            wmma::mma_sync(acc, a_hi[kk], b_hi, acc);
            wmma::mma_sync(acc, a_hi[kk], b_lo, acc);
            wmma::mma_sync(acc, a_lo[kk], b_hi, acc);
        }
        wmma::store_matrix_sync(wOut + n*16, acc, 64, wmma::mem_row_major);
    }
}

// =============================================================================
// Kernel 2: attention + overlap-add finalization (R8 exact).
// =============================================================================
__global__ __launch_bounds__(256) void attn_kernel(float* __restrict__ attn_out)
{
    extern __shared__ float sm[];
    float* Qs = sm;                 // 54*68
    float* Ks = Qs + 54*68;
    float* Vs = Ks + 54*68;
    float* P  = Vs + 54*68;         // 8*144

    const int tid = threadIdx.x;
    const int blk = blockIdx.x;
    const int bh = blk / NG;
    const int g  = blk - bh * NG;
    const int b  = bh >> 3;
    const int h  = bh & 7;

    const int t_start = g * TPB_TOK;
    const int ntok = (LL - t_start < TPB_TOK) ? (LL - t_start) : TPB_TOK;
    const int n_lo = (7*g - 1 < 0) ? 0 : 7*g - 1;
    const int n_hi = (7*g + 6 > NW-1) ? NW-1 : 7*g + 6;
    const int nwin = n_hi - n_lo + 1;
    const int rows = (n_hi - n_lo)*6 + 12;
    const int row0 = n_lo * 6;

    const size_t base = ((size_t)(b*LL + row0)*HH + h) * 64;

    {
        const float* srcs[3] = {g_Qp + base, g_Kp + base, g_Vp + base};
        float* dsts[3] = {Qs, Ks, Vs};
        int nf4 = rows * 16;
        #pragma unroll
        for (int m = 0; m < 3; m++) {
            const float* src = srcs[m];
            float* dst = dsts[m];
            for (int idx = tid; idx < nf4; idx += 256) {
                int row = idx >> 4, c4 = idx & 15;
                float4 val = *reinterpret_cast<const float4*>(src + (size_t)row*512 + c4*4);
                *reinterpret_cast<float4*>(&dst[row*68 + c4*4]) = val;
            }
        }
    }
    __syncthreads();

    for (int o = tid; o < nwin*144; o += 256) {
        int w = o / 144;
        int r = o - w*144;
        int qi = r / 12, ki = r - qi*12;
        const float* qr = &Qs[(w*6 + qi)*68];
        const float* kr = &Ks[(w*6 + ki)*68];
        unsigned long long s01 = 0ULL, s23 = 0ULL;
        #pragma unroll
        for (int d = 0; d < 64; d += 4) {
            float4 a = *reinterpret_cast<const float4*>(&qr[d]);
            float4 bb = *reinterpret_cast<const float4*>(&kr[d]);
            s01 = ffma2(pack2(a.x, a.y), pack2(bb.x, bb.y), s01);
            s23 = ffma2(pack2(a.z, a.w), pack2(bb.z, bb.w), s23);
        }
        float x0, x1, x2, x3;
        unpack2(s01, x0, x1); unpack2(s23, x2, x3);
        P[o] = (x0 + x1 + x2 + x3) * 0.125f;
    }
    __syncthreads();

    for (int t = tid; t < nwin*12; t += 256) {
        int w = t / 12, qi = t - w*12;
        float* row = &P[w*144 + qi*12];
        float mx = row[0];
        #pragma unroll
        for (int k2 = 1; k2 < 12; k2++) mx = fmaxf(mx, row[k2]);
        float sum = 0.f;
        float e[12];
        #pragma unroll
        for (int k2 = 0; k2 < 12; k2++) { e[k2] = __expf(row[k2] - mx); sum += e[k2]; }
        float inv = 1.f / sum;
        #pragma unroll
        for (int k2 = 0; k2 < 12; k2++) row[k2] = e[k2] * inv;
    }
    __syncthreads();

    if (attn_out) {
        int wn0 = 7*g;
        int wn1 = (7*g + 7 < NW) ? 7*g + 7 : NW;
        int nw_out = wn1 - wn0;
        float* dst = attn_out + ((size_t)bh*NW + wn0)*144;
        const float* src = P + (wn0 - n_lo)*144;
        for (int o = tid; o < nw_out*144; o += 256) dst[o] = src[o];
    }

    for (int item = tid; item < ntok*16; item += 256) {
        int t  = t_start + (item >> 4);
        int e4 = (item & 15) * 4;
        int n1 = t / 6;

        unsigned long long a01 = 0ULL, a23 = 0ULL;
        float cnt = 0.f;
        if (n1 <= n_hi) {
            int wi = n1 - n_lo;
            int qq = t - n1*6;
            const float* prow = &P[wi*144 + qq*12];
            const float* vb = &Vs[(wi*6)*68 + e4];
            #pragma unroll
            for (int k2 = 0; k2 < 12; k2++) {
                float4 vv = *reinterpret_cast<const float4*>(&vb[k2*68]);
                unsigned long long pk = pack2(prow[k2], prow[k2]);
                a01 = ffma2(pk, pack2(vv.x, vv.y), a01);
                a23 = ffma2(pk, pack2(vv.z, vv.w), a23);
            }
            cnt += 1.f;
        }
        if (n1 >= 1 && n1 - 1 >= n_lo) {
            int wi = n1 - 1 - n_lo;
            int qq = t - (n1-1)*6;
            const float* prow = &P[wi*144 + qq*12];
            const float* vb = &Vs[(wi*6)*68 + e4];
            #pragma unroll
            for (int k2 = 0; k2 < 12; k2++) {
                float4 vv = *reinterpret_cast<const float4*>(&vb[k2*68]);
                unsigned long long pk = pack2(prow[k2], prow[k2]);
                a01 = ffma2(pk, pack2(vv.x, vv.y), a01);
                a23 = ffma2(pk, pack2(vv.z, vv.w), a23);
            }
            cnt += 1.f;
        }
        float inv = 1.f / cnt;
        float o0, o1, o2, o3;
        unpack2(a01, o0, o1); unpack2(a23, o2, o3);
        *reinterpret_cast<float4*>(
            &g_att[((size_t)(b*LL + t)*HH + h)*64 + e4]) =
            make_float4(o0*inv, o1*inv, o2*inv, o3*inv);
    }
}

// =============================================================================
// Kernel 3: residual + LayerNorm over dense g_att [B,L,512]
// =============================================================================
__global__ __launch_bounds__(128) void combine_kernel(
    const float* __restrict__ queries, const float* __restrict__ gamma,
    const float* __restrict__ beta, float* __restrict__ z)
{
    __shared__ float red[8];

    const int tid = threadIdx.x;
    const int tok = blockIdx.x;
    const int c0 = tid * 4;

    float4 a = *reinterpret_cast<const float4*>(&g_att[(size_t)tok*DM + c0]);
    float4 resid = *reinterpret_cast<const float4*>(&queries[(size_t)tok*DM + c0]);
    float4 x;
    x.x = a.x + resid.x; x.y = a.y + resid.y;
    x.z = a.z + resid.z; x.w = a.w + resid.w;

    float s  = x.x + x.y + x.z + x.w;
    float ss = x.x*x.x + x.y*x.y + x.z*x.z + x.w*x.w;
    #pragma unroll
    for (int off = 16; off > 0; off >>= 1) {
        s  += __shfl_down_sync(0xFFFFFFFFu, s, off);
        ss += __shfl_down_sync(0xFFFFFFFFu, ss, off);
    }
    int wid = tid >> 5, lane = tid & 31;
    if (lane == 0) { red[wid] = s; red[4 + wid] = ss; }
    __syncthreads();
    float ts  = red[0] + red[1] + red[2] + red[3];
    float tss = red[4] + red[5] + red[6] + red[7];
    float mean = ts * (1.f / DM);
    float var  = tss * (1.f / DM) - mean*mean;
    float rstd = rsqrtf(var + LNEPS);

    float4 gg = *reinterpret_cast<const float4*>(&gamma[c0]);
    float4 bta = *reinterpret_cast<const float4*>(&beta[c0]);
    float4 o;
    o.x = (x.x - mean)*rstd*gg.x + bta.x;
    o.y = (x.y - mean)*rstd*gg.y + bta.y;
    o.z = (x.z - mean)*rstd*gg.z + bta.z;
    o.w = (x.w - mean)*rstd*gg.w + bta.w;
    *reinterpret_cast<float4*>(&z[(size_t)tok*DM + c0]) = o;
}

// =============================================================================
extern "C" void kernel_launch(void* const* d_in, const int* in_sizes, int n_in,
                              void* d_out, int out_size) {
    const float* queries = (const float*)d_in[0];
    const float* keys    = (const float*)d_in[1];
    const float* values  = (const float*)d_in[2];
    const float* Wq      = (const float*)d_in[3];
    const float* Wk      = (const float*)d_in[4];
    const float* Wv      = (const float*)d_in[5];
    const float* gamma   = (const float*)d_in[6];
    const float* beta    = (const float*)d_in[7];

    float* z = (float*)d_out;
    const long Z = (long)BB * LL * DM;
    const long A = (long)BB * HH * NW * WS * WS;
    float* attn_out = nullptr;
    if ((long)out_size >= Z + A) attn_out = z + Z;

    const int proj_smem = PROJ_SMEM_BF16 * 2;               // 55296 B
    const int attn_smem = (3*54*68 + 8*144) * 4;            // 48672 B
    static bool attr_set = false;
    if (!attr_set) {
        cudaFuncSetAttribute(proj_kernel, cudaFuncAttributeMaxDynamicSharedMemorySize, proj_smem);
        cudaFuncSetAttribute(attn_kernel, cudaFuncAttributeMaxDynamicSharedMemorySize, attn_smem);
        attr_set = true;
    }

    dim3 pgrid(MROWS/128, 3);
    proj_kernel<<<pgrid, 256, proj_smem>>>(queries, keys, values, Wq, Wk, Wv);
    attn_kernel<<<BB*HH*NG, 256, attn_smem>>>(attn_out);
    combine_kernel<<<BB*LL, 128>>>(queries, gamma, beta, z);
}

// round 17
// speedup vs baseline: 1.4959x; 1.1529x over previous
#include <cuda_runtime.h>
#include <cuda_bf16.h>
#include <mma.h>
#include <math.h>
#include <cstdint>

using namespace nvcuda;

// Problem constants
#define BB 4
#define LL 4092
#define HH 8
#define DH 64
#define DM 512
#define WS 12
#define STEP 6
#define NW 681
#define MROWS (BB*LL*HH)   // 130944
#define LNEPS 1e-5f
#define TPB_TOK 42
#define NG 98              // ceil(4092/42)

// ---------------- scratch -----------------
__device__ float g_Qp[MROWS*DH];          // [B,L,H,64]
__device__ float g_Kp[MROWS*DH];
__device__ float g_Vp[MROWS*DH];
__device__ float g_att[BB*LL*DM];         // averaged attn out [B,L,H*64]

// ---------------- packed f32x2 helpers ----------------
__device__ __forceinline__ unsigned long long ffma2(
    unsigned long long a, unsigned long long b, unsigned long long c) {
    unsigned long long d;
    asm("fma.rn.f32x2 %0, %1, %2, %3;" : "=l"(d) : "l"(a), "l"(b), "l"(c));
    return d;
}
__device__ __forceinline__ unsigned long long pack2(float x, float y) {
    unsigned long long d;
    asm("mov.b64 %0, {%1, %2};" : "=l"(d)
        : "r"(__float_as_uint(x)), "r"(__float_as_uint(y)));
    return d;
}
__device__ __forceinline__ void unpack2(unsigned long long p, float& x, float& y) {
    unsigned int lo, hi;
    asm("mov.b64 {%0, %1}, %2;" : "=r"(lo), "=r"(hi) : "l"(p));
    x = __uint_as_float(lo); y = __uint_as_float(hi);
}

// =============================================================================
// Kernel 1: projections via wmma bf16 split (Ah*Bh + Ah*Bl + Al*Bh).
// grid = (1023, 3). 256 threads = 8 warps; warp w -> rows [w*16, +16).
// W stored UNtransposed in smem [e][d] (vectorized path); matrix_b fragments
// loaded col_major so B[d][e] = W[e][d]. Output direct to global [M][64].
// =============================================================================
#define A_STRIDE 72
#define B_STRIDE 72
#define SM_AH 0
#define SM_AL (128*A_STRIDE)
#define SM_BH (2*128*A_STRIDE)
#define SM_BL (2*128*A_STRIDE + 64*B_STRIDE)
#define PROJ_SMEM_BF16 (2*128*A_STRIDE + 2*64*B_STRIDE)   // 55296 B

__global__ __launch_bounds__(256) void proj_kernel(
    const float* __restrict__ q, const float* __restrict__ k, const float* __restrict__ v,
    const float* __restrict__ Wq, const float* __restrict__ Wk, const float* __restrict__ Wv)
{
    extern __shared__ __nv_bfloat16 smbf[];
    __nv_bfloat16* sAh = smbf + SM_AH;
    __nv_bfloat16* sAl = smbf + SM_AL;
    __nv_bfloat16* sWh = smbf + SM_BH;   // [e][d] layout, stride 72
    __nv_bfloat16* sWl = smbf + SM_BL;

    const int tid = threadIdx.x;
    const int warp = tid >> 5;
    const int r0 = blockIdx.x * 128;
    const int m  = blockIdx.y;

    const float* X = (m == 0) ? q : (m == 1) ? k : v;
    const float* W = (m == 0) ? Wq : (m == 1) ? Wk : Wv;
    float* Out = (m == 0) ? g_Qp : (m == 1) ? g_Kp : g_Vp;

    // ---- W -> bf16 hi/lo, UNtransposed [e][d]; vectorized (float4 in, uint2 out)
    for (int idx = tid; idx < 1024; idx += 256) {        // 1024 float4 of W
        int e = idx >> 4, d4 = idx & 15;
        float4 wv = reinterpret_cast<const float4*>(W)[idx];
        float2 p0 = make_float2(wv.x, wv.y);
        float2 p1 = make_float2(wv.z, wv.w);
        __nv_bfloat162 h0 = __float22bfloat162_rn(p0);
        __nv_bfloat162 h1 = __float22bfloat162_rn(p1);
        float2 hf0 = __bfloat1622float2(h0);
        float2 hf1 = __bfloat1622float2(h1);
        __nv_bfloat162 l0 = __float22bfloat162_rn(make_float2(p0.x - hf0.x, p0.y - hf0.y));
        __nv_bfloat162 l1 = __float22bfloat162_rn(make_float2(p1.x - hf1.x, p1.y - hf1.y));
        uint2 hv, lv;
        hv.x = *reinterpret_cast<uint32_t*>(&h0);
        hv.y = *reinterpret_cast<uint32_t*>(&h1);
        lv.x = *reinterpret_cast<uint32_t*>(&l0);
        lv.y = *reinterpret_cast<uint32_t*>(&l1);
        *reinterpret_cast<uint2*>(&sWh[e*B_STRIDE + d4*4]) = hv;
        *reinterpret_cast<uint2*>(&sWl[e*B_STRIDE + d4*4]) = lv;
    }
    // ---- X -> bf16 hi/lo, row-major [128][72]; vectorized
    for (int idx = tid; idx < 2048; idx += 256) {        // 2048 float4
        int row = idx >> 4, c4 = idx & 15;
        float4 xv = reinterpret_cast<const float4*>(X + (size_t)(r0 + row)*64)[c4];
        float2 p0 = make_float2(xv.x, xv.y);
        float2 p1 = make_float2(xv.z, xv.w);
        __nv_bfloat162 h0 = __float22bfloat162_rn(p0);
        __nv_bfloat162 h1 = __float22bfloat162_rn(p1);
        float2 hf0 = __bfloat1622float2(h0);
        float2 hf1 = __bfloat1622float2(h1);
        __nv_bfloat162 l0 = __float22bfloat162_rn(make_float2(p0.x - hf0.x, p0.y - hf0.y));
        __nv_bfloat162 l1 = __float22bfloat162_rn(make_float2(p1.x - hf1.x, p1.y - hf1.y));
        uint2 hv, lv;
        hv.x = *reinterpret_cast<uint32_t*>(&h0);
        hv.y = *reinterpret_cast<uint32_t*>(&h1);
        lv.x = *reinterpret_cast<uint32_t*>(&l0);
        lv.y = *reinterpret_cast<uint32_t*>(&l1);
        *reinterpret_cast<uint2*>(&sAh[row*A_STRIDE + c4*4]) = hv;
        *reinterpret_cast<uint2*>(&sAl[row*A_STRIDE + c4*4]) = lv;
    }
    __syncthreads();

    // ---- A fragments (4 k-tiles, hi+lo)
    wmma::fragment<wmma::matrix_a, 16, 16, 16, __nv_bfloat16, wmma::row_major> a_hi[4], a_lo[4];
    #pragma unroll
    for (int kk = 0; kk < 4; kk++) {
        wmma::load_matrix_sync(a_hi[kk], &sAh[(warp*16)*A_STRIDE + kk*16], A_STRIDE);
        wmma::load_matrix_sync(a_lo[kk], &sAl[(warp*16)*A_STRIDE + kk*16], A_STRIDE);
    }

    // ---- MMA: 4 n-tiles; B fragments col_major from [e][d] smem
    float* wOut = Out + (size_t)(r0 + warp*16) * 64;
    #pragma unroll
    for (int n = 0; n < 4; n++) {
        wmma::fragment<wmma::accumulator, 16, 16, 16, float> acc;
        wmma::fill_fragment(acc, 0.0f);
        #pragma unroll
        for (int kk = 0; kk < 4; kk++) {
            wmma::fragment<wmma::matrix_b, 16, 16, 16, __nv_bfloat16, wmma::col_major> b_hi, b_lo;
            wmma::load_matrix_sync(b_hi, &sWh[(n*16)*B_STRIDE + kk*16], B_STRIDE);
            wmma::load_matrix_sync(b_lo, &sWl[(n*16)*B_STRIDE + kk*16], B_STRIDE);
            wmma::mma_sync(acc, a_hi[kk], b_hi, acc);
            wmma::mma_sync(acc, a_hi[kk], b_lo, acc);
            wmma::mma_sync(acc, a_lo[kk], b_hi, acc);
        }
        wmma::store_matrix_sync(wOut + n*16, acc, 64, wmma::mem_row_major);
    }
}

// =============================================================================
// Kernel 2: attention + overlap-add finalization (R8 exact).
// =============================================================================
__global__ __launch_bounds__(256) void attn_kernel(float* __restrict__ attn_out)
{
    extern __shared__ float sm[];
    float* Qs = sm;                 // 54*68
    float* Ks = Qs + 54*68;
    float* Vs = Ks + 54*68;
    float* P  = Vs + 54*68;         // 8*144

    const int tid = threadIdx.x;
    const int blk = blockIdx.x;
    const int bh = blk / NG;
    const int g  = blk - bh * NG;
    const int b  = bh >> 3;
    const int h  = bh & 7;

    const int t_start = g * TPB_TOK;
    const int ntok = (LL - t_start < TPB_TOK) ? (LL - t_start) : TPB_TOK;
    const int n_lo = (7*g - 1 < 0) ? 0 : 7*g - 1;
    const int n_hi = (7*g + 6 > NW-1) ? NW-1 : 7*g + 6;
    const int nwin = n_hi - n_lo + 1;
    const int rows = (n_hi - n_lo)*6 + 12;
    const int row0 = n_lo * 6;

    const size_t base = ((size_t)(b*LL + row0)*HH + h) * 64;

    {
        const float* srcs[3] = {g_Qp + base, g_Kp + base, g_Vp + base};
        float* dsts[3] = {Qs, Ks, Vs};
        int nf4 = rows * 16;
        #pragma unroll
        for (int m = 0; m < 3; m++) {
            const float* src = srcs[m];
            float* dst = dsts[m];
            for (int idx = tid; idx < nf4; idx += 256) {
                int row = idx >> 4, c4 = idx & 15;
                float4 val = *reinterpret_cast<const float4*>(src + (size_t)row*512 + c4*4);
                *reinterpret_cast<float4*>(&dst[row*68 + c4*4]) = val;
            }
        }
    }
    __syncthreads();

    for (int o = tid; o < nwin*144; o += 256) {
        int w = o / 144;
        int r = o - w*144;
        int qi = r / 12, ki = r - qi*12;
        const float* qr = &Qs[(w*6 + qi)*68];
        const float* kr = &Ks[(w*6 + ki)*68];
        unsigned long long s01 = 0ULL, s23 = 0ULL;
        #pragma unroll
        for (int d = 0; d < 64; d += 4) {
            float4 a = *reinterpret_cast<const float4*>(&qr[d]);
            float4 bb = *reinterpret_cast<const float4*>(&kr[d]);
            s01 = ffma2(pack2(a.x, a.y), pack2(bb.x, bb.y), s01);
            s23 = ffma2(pack2(a.z, a.w), pack2(bb.z, bb.w), s23);
        }
        float x0, x1, x2, x3;
        unpack2(s01, x0, x1); unpack2(s23, x2, x3);
        P[o] = (x0 + x1 + x2 + x3) * 0.125f;
    }
    __syncthreads();

    for (int t = tid; t < nwin*12; t += 256) {
        int w = t / 12, qi = t - w*12;
        float* row = &P[w*144 + qi*12];
        float mx = row[0];
        #pragma unroll
        for (int k2 = 1; k2 < 12; k2++) mx = fmaxf(mx, row[k2]);
        float sum = 0.f;
        float e[12];
        #pragma unroll
        for (int k2 = 0; k2 < 12; k2++) { e[k2] = __expf(row[k2] - mx); sum += e[k2]; }
        float inv = 1.f / sum;
        #pragma unroll
        for (int k2 = 0; k2 < 12; k2++) row[k2] = e[k2] * inv;
    }
    __syncthreads();

    if (attn_out) {
        int wn0 = 7*g;
        int wn1 = (7*g + 7 < NW) ? 7*g + 7 : NW;
        int nw_out = wn1 - wn0;
        float* dst = attn_out + ((size_t)bh*NW + wn0)*144;
        const float* src = P + (wn0 - n_lo)*144;
        for (int o = tid; o < nw_out*144; o += 256) dst[o] = src[o];
    }

    for (int item = tid; item < ntok*16; item += 256) {
        int t  = t_start + (item >> 4);
        int e4 = (item & 15) * 4;
        int n1 = t / 6;

        unsigned long long a01 = 0ULL, a23 = 0ULL;
        float cnt = 0.f;
        if (n1 <= n_hi) {
            int wi = n1 - n_lo;
            int qq = t - n1*6;
            const float* prow = &P[wi*144 + qq*12];
            const float* vb = &Vs[(wi*6)*68 + e4];
            #pragma unroll
            for (int k2 = 0; k2 < 12; k2++) {
                float4 vv = *reinterpret_cast<const float4*>(&vb[k2*68]);
                unsigned long long pk = pack2(prow[k2], prow[k2]);
                a01 = ffma2(pk, pack2(vv.x, vv.y), a01);
                a23 = ffma2(pk, pack2(vv.z, vv.w), a23);
            }
            cnt += 1.f;
        }
        if (n1 >= 1 && n1 - 1 >= n_lo) {
            int wi = n1 - 1 - n_lo;
            int qq = t - (n1-1)*6;
            const float* prow = &P[wi*144 + qq*12];
            const float* vb = &Vs[(wi*6)*68 + e4];
            #pragma unroll
            for (int k2 = 0; k2 < 12; k2++) {
                float4 vv = *reinterpret_cast<const float4*>(&vb[k2*68]);
                unsigned long long pk = pack2(prow[k2], prow[k2]);
                a01 = ffma2(pk, pack2(vv.x, vv.y), a01);
                a23 = ffma2(pk, pack2(vv.z, vv.w), a23);
            }
            cnt += 1.f;
        }
        float inv = 1.f / cnt;
        float o0, o1, o2, o3;
        unpack2(a01, o0, o1); unpack2(a23, o2, o3);
        *reinterpret_cast<float4*>(
            &g_att[((size_t)(b*LL + t)*HH + h)*64 + e4]) =
            make_float4(o0*inv, o1*inv, o2*inv, o3*inv);
    }
}

// =============================================================================
// Kernel 3: residual + LayerNorm over dense g_att [B,L,512]
// =============================================================================
__global__ __launch_bounds__(128) void combine_kernel(
    const float* __restrict__ queries, const float* __restrict__ gamma,
    const float* __restrict__ beta, float* __restrict__ z)
{
    __shared__ float red[8];

    const int tid = threadIdx.x;
    const int tok = blockIdx.x;
    const int c0 = tid * 4;

    float4 a = *reinterpret_cast<const float4*>(&g_att[(size_t)tok*DM + c0]);
    float4 resid = *reinterpret_cast<const float4*>(&queries[(size_t)tok*DM + c0]);
    float4 x;
    x.x = a.x + resid.x; x.y = a.y + resid.y;
    x.z = a.z + resid.z; x.w = a.w + resid.w;

    float s  = x.x + x.y + x.z + x.w;
    float ss = x.x*x.x + x.y*x.y + x.z*x.z + x.w*x.w;
    #pragma unroll
    for (int off = 16; off > 0; off >>= 1) {
        s  += __shfl_down_sync(0xFFFFFFFFu, s, off);
        ss += __shfl_down_sync(0xFFFFFFFFu, ss, off);
    }
    int wid = tid >> 5, lane = tid & 31;
    if (lane == 0) { red[wid] = s; red[4 + wid] = ss; }
    __syncthreads();
    float ts  = red[0] + red[1] + red[2] + red[3];
    float tss = red[4] + red[5] + red[6] + red[7];
    float mean = ts * (1.f / DM);
    float var  = tss * (1.f / DM) - mean*mean;
    float rstd = rsqrtf(var + LNEPS);

    float4 gg = *reinterpret_cast<const float4*>(&gamma[c0]);
    float4 bta = *reinterpret_cast<const float4*>(&beta[c0]);
    float4 o;
    o.x = (x.x - mean)*rstd*gg.x + bta.x;
    o.y = (x.y - mean)*rstd*gg.y + bta.y;
    o.z = (x.z - mean)*rstd*gg.z + bta.z;
    o.w = (x.w - mean)*rstd*gg.w + bta.w;
    *reinterpret_cast<float4*>(&z[(size_t)tok*DM + c0]) = o;
}

// =============================================================================
extern "C" void kernel_launch(void* const* d_in, const int* in_sizes, int n_in,
                              void* d_out, int out_size) {
    const float* queries = (const float*)d_in[0];
    const float* keys    = (const float*)d_in[1];
    const float* values  = (const float*)d_in[2];
    const float* Wq      = (const float*)d_in[3];
    const float* Wk      = (const float*)d_in[4];
    const float* Wv      = (const float*)d_in[5];
    const float* gamma   = (const float*)d_in[6];
    const float* beta    = (const float*)d_in[7];

    float* z = (float*)d_out;
    const long Z = (long)BB * LL * DM;
    const long A = (long)BB * HH * NW * WS * WS;
    float* attn_out = nullptr;
    if ((long)out_size >= Z + A) attn_out = z + Z;

    const int proj_smem = PROJ_SMEM_BF16 * 2;               // 55296 B
    const int attn_smem = (3*54*68 + 8*144) * 4;            // 48672 B
    static bool attr_set = false;
    if (!attr_set) {
        cudaFuncSetAttribute(proj_kernel, cudaFuncAttributeMaxDynamicSharedMemorySize, proj_smem);
        cudaFuncSetAttribute(attn_kernel, cudaFuncAttributeMaxDynamicSharedMemorySize, attn_smem);
        attr_set = true;
    }

    dim3 pgrid(MROWS/128, 3);
    proj_kernel<<<pgrid, 256, proj_smem>>>(queries, keys, values, Wq, Wk, Wv);
    attn_kernel<<<BB*HH*NG, 256, attn_smem>>>(attn_out);
    combine_kernel<<<BB*LL, 128>>>(queries, gamma, beta, z);
}